// round 2
// baseline (speedup 1.0000x reference)
#include <cuda_runtime.h>
#include <math.h>

#define BB 2
#define CC 128
#define HH 96
#define WW 160
#define HWHW (HH*WW)
#define NDG 16
#define NK2 9
#define CIN0P 392     // 388 padded to multiple of 4
#define COFF 432      // 27 * DG

typedef unsigned long long u64;

__device__ __forceinline__ u64 fma2(u64 a, u64 b, u64 c) {
    u64 d; asm("fma.rn.f32x2 %0, %1, %2, %3;" : "=l"(d) : "l"(a), "l"(b), "l"(c));
    return d;
}
__device__ __forceinline__ float2 unpack2(u64 a) {
    float2 r; asm("mov.b64 {%0,%1}, %2;" : "=f"(r.x), "=f"(r.y) : "l"(a));
    return r;
}

// ---- device-global scratch (no allocations allowed) ----
__device__ float g_ef  [BB*CIN0P*HWHW];
__device__ float g_bufA[BB*CC*HWHW];
__device__ float g_bufB[BB*CC*HWHW];
__device__ float g_h3  [BB*COFF*HWHW];
__device__ float g_val [BB*CC*NK2*HWHW];
__device__ float g_w0p [CC*CIN0P*9];

// ---------------------------------------------------------------------------
__global__ void pack_ef_k(const float* __restrict__ exf,
                          const float* __restrict__ f1,
                          const float* __restrict__ f2)
{
    int idx = blockIdx.x * 256 + threadIdx.x;
    if (idx >= BB*CIN0P*HWHW) return;
    int p = idx % HWHW;
    int c = (idx / HWHW) % CIN0P;
    int b = idx / (CIN0P*HWHW);
    float v = 0.f;
    if (c < 384)      v = exf[(b*384 + c)*HWHW + p];
    else if (c < 386) v = f1[(b*2 + (c-384))*HWHW + p];
    else if (c < 388) v = f2[(b*2 + (c-386))*HWHW + p];
    g_ef[idx] = v;
}

__global__ void pad_w0_k(const float* __restrict__ cw0)
{
    int idx = blockIdx.x * 256 + threadIdx.x;
    if (idx >= CC*CIN0P*9) return;
    int t  = idx % 9;
    int c  = (idx / 9) % CIN0P;
    int oc = idx / (CIN0P*9);
    g_w0p[idx] = (c < 388) ? cw0[(oc*388 + c)*9 + t] : 0.f;
}

// ---------------------------------------------------------------------------
// 3x3 conv, f32x2 packed-FMA version.
// Tile: 64 oc x (16x16) px, 4-in-channel chunks. 256 threads.
// Thread: 8 oc x 4 f32x2 pixel-pairs (8 consecutive px).
// ---------------------------------------------------------------------------
template<bool ACT>
__global__ void __launch_bounds__(256)
conv3_k(const float* __restrict__ in, const float* __restrict__ wgt,
        const float* __restrict__ bias, float* __restrict__ out,
        int CIN, int COUT)
{
    constexpr int CH = 4, PH = 18, PW = 18, PWS = 22;
    constexpr int WST = CH*9 + 1;               // float2 units

    __shared__ __align__(8) float s_in[CH*PH*PWS];
    __shared__ __align__(8) float s_od[CH*PH*PWS];
    __shared__ float2 s_w[64*WST];

    const int tid  = threadIdx.x;
    const int oc_t = tid >> 5;
    const int px_t = tid & 31;
    const int r    = px_t & 15;                 // row 0..15
    const int cg   = (px_t >> 4) << 3;          // 0 or 8

    const int octiles = (COUT + 63) >> 6;
    const int b   = blockIdx.z / octiles;
    const int ocb = (blockIdx.z % octiles) << 6;
    const int w0  = blockIdx.x * 16;
    const int h0  = blockIdx.y * 16;

    u64 acc[8][4];
    #pragma unroll
    for (int j = 0; j < 8; j++)
        #pragma unroll
        for (int p = 0; p < 4; p++) acc[j][p] = 0ull;

    const float* inb = in + (long)b * CIN * HWHW;

    for (int cc = 0; cc < CIN; cc += CH) {
        __syncthreads();
        #pragma unroll 1
        for (int idx = tid; idx < CH*PH*PW; idx += 256) {
            int ci  = idx / (PH*PW);
            int rem = idx - ci*(PH*PW);
            int pr  = rem / PW;
            int pc  = rem - pr*PW;
            int gh  = h0 - 1 + pr;
            int gw  = w0 - 1 + pc;
            float v = 0.f;
            if (gh >= 0 && gh < HH && gw >= 0 && gw < WW)
                v = inb[(cc + ci)*HWHW + gh*WW + gw];
            int sb = ci*(PH*PWS) + pr*PWS + pc;
            s_in[sb] = v;
            if (pc) s_od[sb - 1] = v;
        }
        #pragma unroll 1
        for (int idx = tid; idx < 64*CH*9; idx += 256) {
            int oc = idx / (CH*9);
            int rr = idx - oc*(CH*9);
            int ci = rr / 9;
            int tp = rr - ci*9;
            float v = 0.f;
            if (ocb + oc < COUT)
                v = wgt[((long)(ocb + oc)*CIN + cc + ci)*9 + tp];
            s_w[oc*WST + rr] = make_float2(v, v);
        }
        __syncthreads();

        #pragma unroll 1
        for (int ci = 0; ci < CH; ci++) {
            #pragma unroll
            for (int ky = 0; ky < 3; ky++) {
                const float* rp = &s_in[ci*(PH*PWS) + (r + ky)*PWS + cg];
                const float* ro = &s_od[ci*(PH*PWS) + (r + ky)*PWS + cg];
                u64 e0 = *(const u64*)(rp + 0);
                u64 e1 = *(const u64*)(rp + 2);
                u64 e2 = *(const u64*)(rp + 4);
                u64 e3 = *(const u64*)(rp + 6);
                u64 e4 = *(const u64*)(rp + 8);
                u64 o0 = *(const u64*)(ro + 0);
                u64 o1 = *(const u64*)(ro + 2);
                u64 o2 = *(const u64*)(ro + 4);
                u64 o3 = *(const u64*)(ro + 6);
                const float2* wb = &s_w[(oc_t*8)*WST + ci*9 + ky*3];
                #pragma unroll
                for (int j = 0; j < 8; j++) {
                    u64 wv0 = *(const u64*)(wb + j*WST + 0);
                    u64 wv1 = *(const u64*)(wb + j*WST + 1);
                    u64 wv2 = *(const u64*)(wb + j*WST + 2);
                    acc[j][0] = fma2(wv0, e0, acc[j][0]);
                    acc[j][1] = fma2(wv0, e1, acc[j][1]);
                    acc[j][2] = fma2(wv0, e2, acc[j][2]);
                    acc[j][3] = fma2(wv0, e3, acc[j][3]);
                    acc[j][0] = fma2(wv1, o0, acc[j][0]);
                    acc[j][1] = fma2(wv1, o1, acc[j][1]);
                    acc[j][2] = fma2(wv1, o2, acc[j][2]);
                    acc[j][3] = fma2(wv1, o3, acc[j][3]);
                    acc[j][0] = fma2(wv2, e1, acc[j][0]);
                    acc[j][1] = fma2(wv2, e2, acc[j][1]);
                    acc[j][2] = fma2(wv2, e3, acc[j][2]);
                    acc[j][3] = fma2(wv2, e4, acc[j][3]);
                }
            }
        }
    }

    #pragma unroll
    for (int j = 0; j < 8; j++) {
        int oc = ocb + oc_t*8 + j;
        if (oc < COUT) {
            float bz = bias[oc];
            float v[8];
            #pragma unroll
            for (int p = 0; p < 4; p++) {
                float2 t = unpack2(acc[j][p]);
                v[2*p]   = t.x + bz;
                v[2*p+1] = t.y + bz;
            }
            if (ACT) {
                #pragma unroll
                for (int t = 0; t < 8; t++) v[t] = (v[t] >= 0.f) ? v[t] : 0.1f*v[t];
            }
            float* op = &out[((long)(b*COUT + oc)*HH + (h0 + r))*WW + w0 + cg];
            *(float4*)(op)     = make_float4(v[0], v[1], v[2], v[3]);
            *(float4*)(op + 4) = make_float4(v[4], v[5], v[6], v[7]);
        }
    }
}

// ---------------------------------------------------------------------------
// 1x1 conv (deform contraction over CIN=1152), f32x2 version.
// ---------------------------------------------------------------------------
__global__ void __launch_bounds__(256)
conv1_k(const float* __restrict__ in, const float* __restrict__ wgt,
        const float* __restrict__ bias, float* __restrict__ out,
        int CIN, int COUT)
{
    constexpr int CH = 8, PWS = 18;
    constexpr int WST = CH + 1;                 // float2 units

    __shared__ __align__(8) float s_in[CH*16*PWS];
    __shared__ float2 s_w[64*WST];

    const int tid  = threadIdx.x;
    const int oc_t = tid >> 5;
    const int px_t = tid & 31;
    const int r    = px_t & 15;
    const int cg   = (px_t >> 4) << 3;

    const int octiles = (COUT + 63) >> 6;
    const int b   = blockIdx.z / octiles;
    const int ocb = (blockIdx.z % octiles) << 6;
    const int w0  = blockIdx.x * 16;
    const int h0  = blockIdx.y * 16;

    u64 acc[8][4];
    #pragma unroll
    for (int j = 0; j < 8; j++)
        #pragma unroll
        for (int p = 0; p < 4; p++) acc[j][p] = 0ull;

    const float* inb = in + (long)b * CIN * HWHW;

    for (int cc = 0; cc < CIN; cc += CH) {
        __syncthreads();
        #pragma unroll 1
        for (int idx = tid; idx < CH*256; idx += 256) {
            int ci  = idx >> 8;
            int rem = idx & 255;
            int pr  = rem >> 4;
            int pc  = rem & 15;
            s_in[ci*(16*PWS) + pr*PWS + pc] =
                inb[(cc + ci)*HWHW + (h0 + pr)*WW + w0 + pc];
        }
        #pragma unroll 1
        for (int idx = tid; idx < 64*CH; idx += 256) {
            int oc = idx >> 3;
            int ci = idx & 7;
            float v = 0.f;
            if (ocb + oc < COUT)
                v = wgt[(long)(ocb + oc)*CIN + cc + ci];
            s_w[oc*WST + ci] = make_float2(v, v);
        }
        __syncthreads();

        #pragma unroll 1
        for (int ci = 0; ci < CH; ci++) {
            const float* rp = &s_in[ci*(16*PWS) + r*PWS + cg];
            u64 e0 = *(const u64*)(rp + 0);
            u64 e1 = *(const u64*)(rp + 2);
            u64 e2 = *(const u64*)(rp + 4);
            u64 e3 = *(const u64*)(rp + 6);
            const float2* wb = &s_w[(oc_t*8)*WST + ci];
            #pragma unroll
            for (int j = 0; j < 8; j++) {
                u64 wv = *(const u64*)(wb + j*WST);
                acc[j][0] = fma2(wv, e0, acc[j][0]);
                acc[j][1] = fma2(wv, e1, acc[j][1]);
                acc[j][2] = fma2(wv, e2, acc[j][2]);
                acc[j][3] = fma2(wv, e3, acc[j][3]);
            }
        }
    }

    #pragma unroll
    for (int j = 0; j < 8; j++) {
        int oc = ocb + oc_t*8 + j;
        if (oc < COUT) {
            float bz = bias[oc];
            float v[8];
            #pragma unroll
            for (int p = 0; p < 4; p++) {
                float2 t = unpack2(acc[j][p]);
                v[2*p]   = t.x + bz;
                v[2*p+1] = t.y + bz;
            }
            float* op = &out[((long)(b*COUT + oc)*HH + (h0 + r))*WW + w0 + cg];
            *(float4*)(op)     = make_float4(v[0], v[1], v[2], v[3]);
            *(float4*)(op + 4) = make_float4(v[4], v[5], v[6], v[7]);
        }
    }
}

// ---------------------------------------------------------------------------
// Deform gather (unchanged from passing R1 version).
// ---------------------------------------------------------------------------
__global__ void gather_k(const float* __restrict__ x,
                         const float* __restrict__ f1,
                         const float* __restrict__ f2)
{
    int idx = blockIdx.x * 256 + threadIdx.x;
    if (idx >= BB*NDG*NK2*HWHW) return;

    int w = idx % WW;   int t = idx / WW;
    int h = t % HH;     t /= HH;
    int k = t % NK2;    t /= NK2;
    int dgi = t % NDG;
    int b   = t / NDG;

    int p = h*WW + w;
    const float* fl = (dgi < 8) ? f1 : f2;
    float fy = fl[(b*2 + 1)*HWHW + p];
    float fx = fl[(b*2 + 0)*HWHW + p];

    int coff = (b*COFF + dgi*18 + k*2)*HWHW + p;
    float dy = 10.f * tanhf(g_h3[coff])        + fy;
    float dx = 10.f * tanhf(g_h3[coff + HWHW]) + fx;
    float mk = 1.f / (1.f + expf(-g_h3[(b*COFF + 288 + dgi*9 + k)*HWHW + p]));

    float py = dy + (float)h + (float)(k/3 - 1);
    float px = dx + (float)w + (float)(k%3 - 1);
    float y0f = floorf(py), x0f = floorf(px);
    float wy = py - y0f, wx = px - x0f;
    int y0 = (int)y0f, x0 = (int)x0f;

    bool vy0 = (y0   >= 0) && (y0   < HH);
    bool vy1 = (y0+1 >= 0) && (y0+1 < HH);
    bool vx0 = (x0   >= 0) && (x0   < WW);
    bool vx1 = (x0+1 >= 0) && (x0+1 < WW);

    int y0c = min(max(y0,   0), HH-1);
    int y1c = min(max(y0+1, 0), HH-1);
    int x0c = min(max(x0,   0), WW-1);
    int x1c = min(max(x0+1, 0), WW-1);

    float m00 = (vy0 && vx0) ? (1.f-wy)*(1.f-wx) : 0.f;
    float m01 = (vy0 && vx1) ? (1.f-wy)*wx       : 0.f;
    float m10 = (vy1 && vx0) ? wy*(1.f-wx)       : 0.f;
    float m11 = (vy1 && vx1) ? wy*wx             : 0.f;

    int i00 = y0c*WW + x0c, i01 = y0c*WW + x1c;
    int i10 = y1c*WW + x0c, i11 = y1c*WW + x1c;

    #pragma unroll
    for (int cg = 0; cg < 8; cg++) {
        const float* xp = x + (long)(b*CC + dgi*8 + cg)*HWHW;
        float v = m00*xp[i00] + m01*xp[i01] + m10*xp[i10] + m11*xp[i11];
        g_val[((long)(b*CC + dgi*8 + cg)*NK2 + k)*HWHW + p] = v * mk;
    }
}

// ---------------------------------------------------------------------------
extern "C" void kernel_launch(void* const* d_in, const int* in_sizes, int n_in,
                              void* d_out, int out_size)
{
    const float* x    = (const float*)d_in[0];
    const float* exf  = (const float*)d_in[1];
    const float* f1   = (const float*)d_in[2];
    const float* f2   = (const float*)d_in[3];
    const float* wgt  = (const float*)d_in[4];
    const float* bias = (const float*)d_in[5];
    const float* cw0  = (const float*)d_in[6];
    const float* cb0  = (const float*)d_in[7];
    const float* cw1  = (const float*)d_in[8];
    const float* cb1  = (const float*)d_in[9];
    const float* cw2  = (const float*)d_in[10];
    const float* cb2  = (const float*)d_in[11];
    const float* cw3  = (const float*)d_in[12];
    const float* cb3  = (const float*)d_in[13];
    float* out = (float*)d_out;

    void *p_ef, *p_A, *p_B, *p_h3, *p_val, *p_w0p;
    cudaGetSymbolAddress(&p_ef,  g_ef);
    cudaGetSymbolAddress(&p_A,   g_bufA);
    cudaGetSymbolAddress(&p_B,   g_bufB);
    cudaGetSymbolAddress(&p_h3,  g_h3);
    cudaGetSymbolAddress(&p_val, g_val);
    cudaGetSymbolAddress(&p_w0p, g_w0p);

    pack_ef_k<<<(BB*CIN0P*HWHW + 255)/256, 256>>>(exf, f1, f2);
    pad_w0_k<<<(CC*CIN0P*9 + 255)/256, 256>>>(cw0);

    dim3 g128(WW/16, HH/16, BB * 2);             // 10 x 6 x 4
    conv3_k<true ><<<g128, 256>>>((const float*)p_ef, (const float*)p_w0p, cb0,
                                  (float*)p_A, CIN0P, 128);
    conv3_k<true ><<<g128, 256>>>((const float*)p_A, cw1, cb1,
                                  (float*)p_B, 128, 128);
    conv3_k<true ><<<g128, 256>>>((const float*)p_B, cw2, cb2,
                                  (float*)p_A, 128, 128);

    dim3 g432(WW/16, HH/16, BB * 7);             // 10 x 6 x 14
    conv3_k<false><<<g432, 256>>>((const float*)p_A, cw3, cb3,
                                  (float*)p_h3, 128, COFF);

    gather_k<<<(BB*NDG*NK2*HWHW + 255)/256, 256>>>(x, f1, f2);

    conv1_k<<<g128, 256>>>((const float*)p_val, wgt, bias,
                           out, CC*NK2, 128);
}

// round 5
// speedup vs baseline: 1.6876x; 1.6876x over previous
#include <cuda_runtime.h>
#include <cuda_bf16.h>
#include <math.h>
#include <stdint.h>

#define BB 2
#define CC 128
#define HH 96
#define WW 160
#define HWHW (HH*WW)
#define PH98 98
#define PW162 162
#define NPIX (BB*HWHW)
#define COFF 432
#define CIN0P 400
#define KFIN 1152

typedef unsigned long long u64;
typedef __nv_bfloat16 bf16;

// ---------------- device-global scratch ----------------
__device__ __align__(16) bf16 g_ef_hi [BB*PH98*PW162*CIN0P];
__device__ __align__(16) bf16 g_ef_lo [BB*PH98*PW162*CIN0P];
__device__ __align__(16) bf16 g_bA_hi [BB*PH98*PW162*CC];
__device__ __align__(16) bf16 g_bA_lo [BB*PH98*PW162*CC];
__device__ __align__(16) bf16 g_bB_hi [BB*PH98*PW162*CC];
__device__ __align__(16) bf16 g_bB_lo [BB*PH98*PW162*CC];
__device__ float g_h3 [BB*COFF*HWHW];
__device__ __align__(16) bf16 g_val_hi[(long)NPIX*KFIN];
__device__ __align__(16) bf16 g_val_lo[(long)NPIX*KFIN];
__device__ __align__(16) bf16 g_w0_hi [9*CC*CIN0P];
__device__ __align__(16) bf16 g_w0_lo [9*CC*CIN0P];
__device__ __align__(16) bf16 g_w1_hi [9*CC*CC];
__device__ __align__(16) bf16 g_w1_lo [9*CC*CC];
__device__ __align__(16) bf16 g_w2_hi [9*CC*CC];
__device__ __align__(16) bf16 g_w2_lo [9*CC*CC];
__device__ __align__(16) bf16 g_w3_hi [9*512*CC];
__device__ __align__(16) bf16 g_w3_lo [9*512*CC];
__device__ __align__(16) bf16 g_wf_hi [CC*KFIN];
__device__ __align__(16) bf16 g_wf_lo [CC*KFIN];

// ---------------- helpers ----------------
__device__ __forceinline__ uint32_t smem_u32(const void* p) {
    uint32_t a;
    asm("{ .reg .u64 t; cvta.to.shared.u64 t, %1; cvt.u32.u64 %0, t; }" : "=r"(a) : "l"(p));
    return a;
}
__device__ __forceinline__ void ldsm4(uint32_t* r, uint32_t a) {
    asm volatile("ldmatrix.sync.aligned.m8n8.x4.shared.b16 {%0,%1,%2,%3}, [%4];"
                 : "=r"(r[0]), "=r"(r[1]), "=r"(r[2]), "=r"(r[3]) : "r"(a));
}
__device__ __forceinline__ void ldsm2(uint32_t* r, uint32_t a) {
    asm volatile("ldmatrix.sync.aligned.m8n8.x2.shared.b16 {%0,%1}, [%2];"
                 : "=r"(r[0]), "=r"(r[1]) : "r"(a));
}
__device__ __forceinline__ void mma_bf16(float* d, const uint32_t* a, const uint32_t* b) {
    asm volatile("mma.sync.aligned.m16n8k16.row.col.f32.bf16.bf16.f32 "
                 "{%0,%1,%2,%3}, {%4,%5,%6,%7}, {%8,%9}, {%0,%1,%2,%3};"
                 : "+f"(d[0]), "+f"(d[1]), "+f"(d[2]), "+f"(d[3])
                 : "r"(a[0]), "r"(a[1]), "r"(a[2]), "r"(a[3]), "r"(b[0]), "r"(b[1]));
}
__device__ __forceinline__ void split_bf16(float v, bf16& hi, bf16& lo) {
    hi = __float2bfloat16(v);
    lo = __float2bfloat16(v - __bfloat162float(hi));
}

// ---------------- prep kernels ----------------
__global__ void zero_bufs_k() {
    int i = blockIdx.x * 256 + threadIdx.x;
    if (i >= BB*PH98*PW162*CC) return;
    bf16 z = __float2bfloat16(0.f);
    g_bA_hi[i] = z; g_bA_lo[i] = z; g_bB_hi[i] = z; g_bB_lo[i] = z;
}

__global__ void pack_ef_k(const float* __restrict__ exf, const float* __restrict__ f1,
                          const float* __restrict__ f2) {
    int i = blockIdx.x * 256 + threadIdx.x;
    if (i >= BB*PH98*PW162*CIN0P) return;
    int c  = i % CIN0P;
    int pw = (i / CIN0P) % PW162;
    int ph = (i / (CIN0P*PW162)) % PH98;
    int b  = i / (CIN0P*PW162*PH98);
    float v = 0.f;
    if (ph >= 1 && ph <= HH && pw >= 1 && pw <= WW && c < 388) {
        int p = (ph-1)*WW + (pw-1);
        if (c < 384)      v = exf[(b*384 + c)*HWHW + p];
        else if (c < 386) v = f1[(b*2 + (c-384))*HWHW + p];
        else              v = f2[(b*2 + (c-386))*HWHW + p];
    }
    bf16 hi, lo; split_bf16(v, hi, lo);
    g_ef_hi[i] = hi; g_ef_lo[i] = lo;
}

__global__ void wprep_k(const float* __restrict__ src, bf16* __restrict__ dHi,
                        bf16* __restrict__ dLo, int COUT, int CIN, int CINP, int COUTP) {
    int i = blockIdx.x * 256 + threadIdx.x;
    if (i >= 9*COUTP*CINP) return;
    int ci  = i % CINP;
    int oc  = (i / CINP) % COUTP;
    int tap = i / (CINP*COUTP);
    float v = (oc < COUT && ci < CIN) ? src[((long)oc*CIN + ci)*9 + tap] : 0.f;
    bf16 hi, lo; split_bf16(v, hi, lo);
    dHi[i] = hi; dLo[i] = lo;
}

__global__ void wprep_fin_k(const float* __restrict__ src) {
    int i = blockIdx.x * 256 + threadIdx.x;
    if (i >= CC*KFIN) return;
    int k  = i % KFIN;
    int oc = i / KFIN;
    int ci = k / 9, tap = k % 9;
    float v = src[((long)oc*CC + ci)*9 + tap];
    bf16 hi, lo; split_bf16(v, hi, lo);
    g_wf_hi[i] = hi; g_wf_lo[i] = lo;
}

// ---------------- deform gather -> val[pix][ci*9+tap], bf16 hi/lo -----------
__global__ void gather_k(const float* __restrict__ x, const float* __restrict__ f1,
                         const float* __restrict__ f2) {
    int idx = blockIdx.x * 256 + threadIdx.x;
    if (idx >= BB*16*9*HWHW) return;
    int w = idx % WW;   int t = idx / WW;
    int h = t % HH;     t /= HH;
    int k = t % 9;      t /= 9;
    int dgi = t % 16;
    int b   = t / 16;

    int p = h*WW + w;
    const float* fl = (dgi < 8) ? f1 : f2;
    float fy = fl[(b*2 + 1)*HWHW + p];
    float fx = fl[(b*2 + 0)*HWHW + p];

    int coff = (b*COFF + dgi*18 + k*2)*HWHW + p;
    float dy = 10.f * tanhf(g_h3[coff])        + fy;
    float dx = 10.f * tanhf(g_h3[coff + HWHW]) + fx;
    float mk = 1.f / (1.f + expf(-g_h3[(b*COFF + 288 + dgi*9 + k)*HWHW + p]));

    float py = dy + (float)h + (float)(k/3 - 1);
    float px = dx + (float)w + (float)(k%3 - 1);
    float y0f = floorf(py), x0f = floorf(px);
    float wy = py - y0f, wx = px - x0f;
    int y0 = (int)y0f, x0 = (int)x0f;

    bool vy0 = (y0 >= 0) && (y0 < HH);
    bool vy1 = (y0+1 >= 0) && (y0+1 < HH);
    bool vx0 = (x0 >= 0) && (x0 < WW);
    bool vx1 = (x0+1 >= 0) && (x0+1 < WW);
    int y0c = min(max(y0, 0), HH-1),  y1c = min(max(y0+1, 0), HH-1);
    int x0c = min(max(x0, 0), WW-1),  x1c = min(max(x0+1, 0), WW-1);
    float m00 = (vy0 && vx0) ? (1.f-wy)*(1.f-wx) : 0.f;
    float m01 = (vy0 && vx1) ? (1.f-wy)*wx       : 0.f;
    float m10 = (vy1 && vx0) ? wy*(1.f-wx)       : 0.f;
    float m11 = (vy1 && vx1) ? wy*wx             : 0.f;
    int i00 = y0c*WW + x0c, i01 = y0c*WW + x1c;
    int i10 = y1c*WW + x0c, i11 = y1c*WW + x1c;

    long pix = (long)(b*HH + h)*WW + w;
    #pragma unroll
    for (int cg = 0; cg < 8; cg++) {
        const float* xp = x + (long)(b*CC + dgi*8 + cg)*HWHW;
        float v = (m00*xp[i00] + m01*xp[i01] + m10*xp[i10] + m11*xp[i11]) * mk;
        bf16 hi, lo; split_bf16(v, hi, lo);
        long di = pix*KFIN + (dgi*8 + cg)*9 + k;
        g_val_hi[di] = hi; g_val_lo[di] = lo;
    }
}

// ---------------- mma.sync conv/GEMM kernel ----------------
// CTA: one pixel row (h), M=128 oc (mt selects 128-slice), N=160 px.
// 8 warps 2x4; warp tile 64x40 = 4x5 m16n8 tiles. bf16 hi/lo 3-term.
// EPI 0: +bias, lrelu -> bf16 hi/lo NHWC padded. EPI 1: +bias -> f32 NCHW.
template<int KC, int TAPS, int EPI>
__global__ void __launch_bounds__(256, 1)
mma_conv_k(const bf16* __restrict__ wHi, const bf16* __restrict__ wLo,
           const bf16* __restrict__ bHi, const bf16* __restrict__ bLo,
           const float* __restrict__ bias,
           float* __restrict__ outF, bf16* __restrict__ outHi, bf16* __restrict__ outLo,
           int CINP, int MT, int COUT)
{
    constexpr bool HALO = (TAPS == 9);
    constexpr int STR   = (KC + 8) * 2;           // smem row stride bytes
    constexpr int ASZ1  = 128 * STR;              // per-tap A tile
    constexpr int BROWS = HALO ? 3*PW162 : WW;
    constexpr int OFF_AL = TAPS * ASZ1;
    constexpr int OFF_BH = 2 * TAPS * ASZ1;
    constexpr int OFF_BL = OFF_BH + BROWS * STR;
    constexpr int K8    = KC / 8;

    extern __shared__ __align__(16) char sm[];
    const uint32_t sb = smem_u32(sm);

    const int tid  = threadIdx.x;
    const int wid  = tid >> 5;
    const int lane = tid & 31;
    const int wm   = wid & 1;          // 0..1 -> m offset 0/64
    const int wn   = wid >> 1;         // 0..3 -> n offset 0/40/80/120

    const int h  = blockIdx.x;
    const int b  = blockIdx.z / MT;
    const int mt = blockIdx.z % MT;

    float acc[20][4];
    #pragma unroll
    for (int i = 0; i < 20; i++)
        #pragma unroll
        for (int j = 0; j < 4; j++) acc[i][j] = 0.f;

    // lane-fixed ldmatrix offsets
    const uint32_t aoff  = (lane & 15)*STR + (lane >> 4)*16 + wm*64*STR;
    const uint32_t boff4 = ((lane & 7) + ((lane >> 4) << 3))*STR + ((lane >> 3) & 1)*16;
    const uint32_t boff2 = (lane & 7)*STR + ((lane >> 3) & 1)*16;

    const int NCH = CINP / KC;
    for (int ch = 0; ch < NCH; ch++) {
        const int cc = ch * KC;
        if (ch) __syncthreads();

        // ---- stage A: [tap][128][KC] hi+lo ----
        {
            const int cnt = TAPS*128*K8;
            #pragma unroll 1
            for (int idx = tid; idx < cnt; idx += 256) {
                int k8  = idx % K8;
                int m   = (idx / K8) % 128;
                int tap = idx / (K8*128);
                long s  = ((long)(tap*MT*128 + mt*128 + m))*CINP + cc + k8*8;
                int  d  = tap*ASZ1 + m*STR + k8*16;
                *(uint4*)(sm + d)          = *(const uint4*)(wHi + s);
                *(uint4*)(sm + OFF_AL + d) = *(const uint4*)(wLo + s);
            }
        }
        // ---- stage B rows ----
        {
            const int cnt = BROWS*K8;
            #pragma unroll 1
            for (int idx = tid; idx < cnt; idx += 256) {
                int k8 = idx % K8;
                int rw = idx / K8;
                long s;
                if (HALO) {
                    int pw = rw % PW162, ky = rw / PW162;
                    s = ((long)((b*PH98 + h + ky)*PW162 + pw))*CINP + cc + k8*8;
                } else {
                    s = ((long)((b*HH + h)*WW + rw))*CINP + cc + k8*8;
                }
                int d = rw*STR + k8*16;
                *(uint4*)(sm + OFF_BH + d) = *(const uint4*)(bHi + s);
                *(uint4*)(sm + OFF_BL + d) = *(const uint4*)(bLo + s);
            }
        }
        __syncthreads();

        #pragma unroll 1
        for (int ks = 0; ks < KC/16; ks++) {
            const uint32_t koff = ks*32;
            #pragma unroll 1
            for (int tap = 0; tap < TAPS; tap++) {
                uint32_t ah[4][4], al[4][4], bh[5][2], bl[5][2];
                const uint32_t abase = sb + tap*ASZ1 + aoff + koff;
                #pragma unroll
                for (int m = 0; m < 4; m++) {
                    ldsm4(ah[m], abase + m*16*STR);
                    ldsm4(al[m], abase + OFF_AL + m*16*STR);
                }
                int brow;
                if (HALO) { int ky = tap/3, kx = tap - 3*(tap/3); brow = ky*PW162 + wn*40 + kx; }
                else      { brow = wn*40; }
                const uint32_t bb = sb + OFF_BH + brow*STR + koff;
                ldsm4(&bh[0][0], bb + boff4);
                ldsm4(&bh[2][0], bb + 16*STR + boff4);
                ldsm2(&bh[4][0], bb + 32*STR + boff2);
                const uint32_t bbl = bb + (OFF_BL - OFF_BH);
                ldsm4(&bl[0][0], bbl + boff4);
                ldsm4(&bl[2][0], bbl + 16*STR + boff4);
                ldsm2(&bl[4][0], bbl + 32*STR + boff2);

                #pragma unroll
                for (int n = 0; n < 5; n++)
                    #pragma unroll
                    for (int m = 0; m < 4; m++)
                        mma_bf16(acc[m*5+n], ah[m], bh[n]);
                #pragma unroll
                for (int n = 0; n < 5; n++)
                    #pragma unroll
                    for (int m = 0; m < 4; m++)
                        mma_bf16(acc[m*5+n], ah[m], bl[n]);
                #pragma unroll
                for (int n = 0; n < 5; n++)
                    #pragma unroll
                    for (int m = 0; m < 4; m++)
                        mma_bf16(acc[m*5+n], al[m], bh[n]);
            }
        }
    }

    // ---- epilogue ----
    #pragma unroll
    for (int m = 0; m < 4; m++) {
        #pragma unroll
        for (int half = 0; half < 2; half++) {
            int ml = wm*64 + m*16 + (lane >> 2) + half*8;     // 0..127
            int oc = mt*128 + ml;
            if (oc >= COUT) continue;
            float bz = bias[oc];
            #pragma unroll
            for (int n = 0; n < 5; n++) {
                int nn = wn*40 + n*8 + (lane & 3)*2;
                float v0 = acc[m*5+n][half*2+0] + bz;
                float v1 = acc[m*5+n][half*2+1] + bz;
                if (EPI == 0) {
                    v0 = (v0 >= 0.f) ? v0 : 0.1f*v0;
                    v1 = (v1 >= 0.f) ? v1 : 0.1f*v1;
                    long d0 = ((long)(b*PH98 + h + 1)*PW162 + 1 + nn)*CC + ml;
                    bf16 h0, l0, h1, l1;
                    split_bf16(v0, h0, l0); split_bf16(v1, h1, l1);
                    outHi[d0] = h0;      outLo[d0] = l0;
                    outHi[d0 + CC] = h1; outLo[d0 + CC] = l1;
                } else {
                    float2 o; o.x = v0; o.y = v1;
                    *(float2*)(outF + ((long)(b*COUT + oc)*HH + h)*WW + nn) = o;
                }
            }
        }
    }
}

// ---------------- launcher ----------------
#define SMEM_HALO (2*9*128*48 + 2*3*PW162*48)        // 157248
#define SMEM_1x1  (2*128*144 + 2*WW*144)             // 82944

extern "C" void kernel_launch(void* const* d_in, const int* in_sizes, int n_in,
                              void* d_out, int out_size)
{
    const float* x    = (const float*)d_in[0];
    const float* exf  = (const float*)d_in[1];
    const float* f1   = (const float*)d_in[2];
    const float* f2   = (const float*)d_in[3];
    const float* wgt  = (const float*)d_in[4];
    const float* bias = (const float*)d_in[5];
    const float* cw0  = (const float*)d_in[6];
    const float* cb0  = (const float*)d_in[7];
    const float* cw1  = (const float*)d_in[8];
    const float* cb1  = (const float*)d_in[9];
    const float* cw2  = (const float*)d_in[10];
    const float* cb2  = (const float*)d_in[11];
    const float* cw3  = (const float*)d_in[12];
    const float* cb3  = (const float*)d_in[13];
    float* out = (float*)d_out;

    cudaFuncSetAttribute(mma_conv_k<16,9,0>, cudaFuncAttributeMaxDynamicSharedMemorySize, SMEM_HALO);
    cudaFuncSetAttribute(mma_conv_k<16,9,1>, cudaFuncAttributeMaxDynamicSharedMemorySize, SMEM_HALO);
    cudaFuncSetAttribute(mma_conv_k<64,1,1>, cudaFuncAttributeMaxDynamicSharedMemorySize, SMEM_1x1);

    void *pefh, *pefl, *pAh, *pAl, *pBh, *pBl, *ph3, *pvh, *pvl;
    void *pw0h, *pw0l, *pw1h, *pw1l, *pw2h, *pw2l, *pw3h, *pw3l, *pwfh, *pwfl;
    cudaGetSymbolAddress(&pefh, g_ef_hi);  cudaGetSymbolAddress(&pefl, g_ef_lo);
    cudaGetSymbolAddress(&pAh, g_bA_hi);   cudaGetSymbolAddress(&pAl, g_bA_lo);
    cudaGetSymbolAddress(&pBh, g_bB_hi);   cudaGetSymbolAddress(&pBl, g_bB_lo);
    cudaGetSymbolAddress(&ph3, g_h3);
    cudaGetSymbolAddress(&pvh, g_val_hi);  cudaGetSymbolAddress(&pvl, g_val_lo);
    cudaGetSymbolAddress(&pw0h, g_w0_hi);  cudaGetSymbolAddress(&pw0l, g_w0_lo);
    cudaGetSymbolAddress(&pw1h, g_w1_hi);  cudaGetSymbolAddress(&pw1l, g_w1_lo);
    cudaGetSymbolAddress(&pw2h, g_w2_hi);  cudaGetSymbolAddress(&pw2l, g_w2_lo);
    cudaGetSymbolAddress(&pw3h, g_w3_hi);  cudaGetSymbolAddress(&pw3l, g_w3_lo);
    cudaGetSymbolAddress(&pwfh, g_wf_hi);  cudaGetSymbolAddress(&pwfl, g_wf_lo);

    zero_bufs_k<<<(BB*PH98*PW162*CC + 255)/256, 256>>>();
    pack_ef_k<<<(BB*PH98*PW162*CIN0P + 255)/256, 256>>>(exf, f1, f2);
    wprep_k<<<(9*CC*CIN0P + 255)/256, 256>>>(cw0, (bf16*)pw0h, (bf16*)pw0l, 128, 388, CIN0P, 128);
    wprep_k<<<(9*CC*CC   + 255)/256, 256>>>(cw1, (bf16*)pw1h, (bf16*)pw1l, 128, 128, 128, 128);
    wprep_k<<<(9*CC*CC   + 255)/256, 256>>>(cw2, (bf16*)pw2h, (bf16*)pw2l, 128, 128, 128, 128);
    wprep_k<<<(9*512*CC  + 255)/256, 256>>>(cw3, (bf16*)pw3h, (bf16*)pw3l, COFF, 128, 128, 512);
    wprep_fin_k<<<(CC*KFIN + 255)/256, 256>>>(wgt);

    dim3 g1(HH, 1, BB);
    mma_conv_k<16,9,0><<<g1, 256, SMEM_HALO>>>(
        (const bf16*)pw0h, (const bf16*)pw0l, (const bf16*)pefh, (const bf16*)pefl,
        cb0, nullptr, (bf16*)pAh, (bf16*)pAl, CIN0P, 1, 128);
    mma_conv_k<16,9,0><<<g1, 256, SMEM_HALO>>>(
        (const bf16*)pw1h, (const bf16*)pw1l, (const bf16*)pAh, (const bf16*)pAl,
        cb1, nullptr, (bf16*)pBh, (bf16*)pBl, 128, 1, 128);
    mma_conv_k<16,9,0><<<g1, 256, SMEM_HALO>>>(
        (const bf16*)pw2h, (const bf16*)pw2l, (const bf16*)pBh, (const bf16*)pBl,
        cb2, nullptr, (bf16*)pAh, (bf16*)pAl, 128, 1, 128);

    dim3 g3(HH, 1, BB*4);
    mma_conv_k<16,9,1><<<g3, 256, SMEM_HALO>>>(
        (const bf16*)pw3h, (const bf16*)pw3l, (const bf16*)pAh, (const bf16*)pAl,
        cb3, (float*)ph3, nullptr, nullptr, 128, 4, COFF);

    gather_k<<<(BB*16*9*HWHW + 255)/256, 256>>>(x, f1, f2);

    mma_conv_k<64,1,1><<<g1, 256, SMEM_1x1>>>(
        (const bf16*)pwfh, (const bf16*)pwfl, (const bf16*)pvh, (const bf16*)pvl,
        bias, out, nullptr, nullptr, KFIN, 1, 128);
}

// round 7
// speedup vs baseline: 1.8099x; 1.0725x over previous
#include <cuda_runtime.h>
#include <cuda_bf16.h>
#include <math.h>
#include <stdint.h>

#define BB 2
#define CC 128
#define HH 96
#define WW 160
#define HWHW (HH*WW)
#define PH98 98
#define PW162 162
#define NPIX (BB*HWHW)
#define COFF 432
#define CIN0P 400
#define KFIN 1152

typedef unsigned long long u64;
typedef __nv_bfloat16 bf16;

// ---------------- device-global scratch ----------------
__device__ __align__(16) bf16 g_ef_hi [BB*PH98*PW162*CIN0P];
__device__ __align__(16) bf16 g_ef_lo [BB*PH98*PW162*CIN0P];
__device__ __align__(16) bf16 g_bA_hi [BB*PH98*PW162*CC];
__device__ __align__(16) bf16 g_bA_lo [BB*PH98*PW162*CC];
__device__ __align__(16) bf16 g_bB_hi [BB*PH98*PW162*CC];
__device__ __align__(16) bf16 g_bB_lo [BB*PH98*PW162*CC];
__device__ float g_h3 [BB*COFF*HWHW];
__device__ __align__(16) bf16 g_val_hi[(long)NPIX*KFIN];
__device__ __align__(16) bf16 g_val_lo[(long)NPIX*KFIN];
__device__ __align__(16) bf16 g_w0_hi [9*CC*CIN0P];
__device__ __align__(16) bf16 g_w0_lo [9*CC*CIN0P];
__device__ __align__(16) bf16 g_w1_hi [9*CC*CC];
__device__ __align__(16) bf16 g_w1_lo [9*CC*CC];
__device__ __align__(16) bf16 g_w2_hi [9*CC*CC];
__device__ __align__(16) bf16 g_w2_lo [9*CC*CC];
__device__ __align__(16) bf16 g_w3_hi [9*512*CC];
__device__ __align__(16) bf16 g_w3_lo [9*512*CC];
__device__ __align__(16) bf16 g_wf_hi [CC*KFIN];
__device__ __align__(16) bf16 g_wf_lo [CC*KFIN];

// ---------------- helpers ----------------
__device__ __forceinline__ uint32_t smem_u32(const void* p) {
    uint32_t a;
    asm("{ .reg .u64 t; cvta.to.shared.u64 t, %1; cvt.u32.u64 %0, t; }" : "=r"(a) : "l"(p));
    return a;
}
__device__ __forceinline__ void ldsm4(uint32_t* r, uint32_t a) {
    asm volatile("ldmatrix.sync.aligned.m8n8.x4.shared.b16 {%0,%1,%2,%3}, [%4];"
                 : "=r"(r[0]), "=r"(r[1]), "=r"(r[2]), "=r"(r[3]) : "r"(a));
}
__device__ __forceinline__ void ldsm2(uint32_t* r, uint32_t a) {
    asm volatile("ldmatrix.sync.aligned.m8n8.x2.shared.b16 {%0,%1}, [%2];"
                 : "=r"(r[0]), "=r"(r[1]) : "r"(a));
}
__device__ __forceinline__ void mma_bf16(float* d, const uint32_t* a, const uint32_t* b) {
    asm volatile("mma.sync.aligned.m16n8k16.row.col.f32.bf16.bf16.f32 "
                 "{%0,%1,%2,%3}, {%4,%5,%6,%7}, {%8,%9}, {%0,%1,%2,%3};"
                 : "+f"(d[0]), "+f"(d[1]), "+f"(d[2]), "+f"(d[3])
                 : "r"(a[0]), "r"(a[1]), "r"(a[2]), "r"(a[3]), "r"(b[0]), "r"(b[1]));
}
__device__ __forceinline__ void split_bf16(float v, bf16& hi, bf16& lo) {
    hi = __float2bfloat16(v);
    lo = __float2bfloat16(v - __bfloat162float(hi));
}
#define CP16(d, s)  asm volatile("cp.async.cg.shared.global [%0], [%1], 16;" :: "r"(d), "l"(s))
#define CPCOMMIT()  asm volatile("cp.async.commit_group;" ::: "memory")
#define CPWAIT0()   asm volatile("cp.async.wait_group 0;" ::: "memory")
#define CPWAIT1()   asm volatile("cp.async.wait_group 1;" ::: "memory")

// ---------------- prep kernels ----------------
__global__ void zero_bufs_k() {
    int i = blockIdx.x * 256 + threadIdx.x;
    if (i >= BB*PH98*PW162*CC) return;
    bf16 z = __float2bfloat16(0.f);
    g_bA_hi[i] = z; g_bA_lo[i] = z; g_bB_hi[i] = z; g_bB_lo[i] = z;
}

__global__ void pack_ef_k(const float* __restrict__ exf, const float* __restrict__ f1,
                          const float* __restrict__ f2) {
    int i = blockIdx.x * 256 + threadIdx.x;
    if (i >= BB*PH98*PW162*CIN0P) return;
    int c  = i % CIN0P;
    int pw = (i / CIN0P) % PW162;
    int ph = (i / (CIN0P*PW162)) % PH98;
    int b  = i / (CIN0P*PW162*PH98);
    float v = 0.f;
    if (ph >= 1 && ph <= HH && pw >= 1 && pw <= WW && c < 388) {
        int p = (ph-1)*WW + (pw-1);
        if (c < 384)      v = exf[(b*384 + c)*HWHW + p];
        else if (c < 386) v = f1[(b*2 + (c-384))*HWHW + p];
        else              v = f2[(b*2 + (c-386))*HWHW + p];
    }
    bf16 hi, lo; split_bf16(v, hi, lo);
    g_ef_hi[i] = hi; g_ef_lo[i] = lo;
}

__global__ void wprep_k(const float* __restrict__ src, bf16* __restrict__ dHi,
                        bf16* __restrict__ dLo, int COUT, int CIN, int CINP, int COUTP) {
    int i = blockIdx.x * 256 + threadIdx.x;
    if (i >= 9*COUTP*CINP) return;
    int ci  = i % CINP;
    int oc  = (i / CINP) % COUTP;
    int tap = i / (CINP*COUTP);
    float v = (oc < COUT && ci < CIN) ? src[((long)oc*CIN + ci)*9 + tap] : 0.f;
    bf16 hi, lo; split_bf16(v, hi, lo);
    dHi[i] = hi; dLo[i] = lo;
}

__global__ void wprep_fin_k(const float* __restrict__ src) {
    int i = blockIdx.x * 256 + threadIdx.x;
    if (i >= CC*KFIN) return;
    int k  = i % KFIN;
    int oc = i / KFIN;
    int ci = k / 9, tap = k % 9;
    float v = src[((long)oc*CC + ci)*9 + tap];
    bf16 hi, lo; split_bf16(v, hi, lo);
    g_wf_hi[i] = hi; g_wf_lo[i] = lo;
}

// ---------------- deform gather ----------------
__global__ void gather_k(const float* __restrict__ x, const float* __restrict__ f1,
                         const float* __restrict__ f2) {
    int idx = blockIdx.x * 256 + threadIdx.x;
    if (idx >= BB*16*9*HWHW) return;
    int w = idx % WW;   int t = idx / WW;
    int h = t % HH;     t /= HH;
    int k = t % 9;      t /= 9;
    int dgi = t % 16;
    int b   = t / 16;

    int p = h*WW + w;
    const float* fl = (dgi < 8) ? f1 : f2;
    float fy = fl[(b*2 + 1)*HWHW + p];
    float fx = fl[(b*2 + 0)*HWHW + p];

    int coff = (b*COFF + dgi*18 + k*2)*HWHW + p;
    float dy = 10.f * tanhf(g_h3[coff])        + fy;
    float dx = 10.f * tanhf(g_h3[coff + HWHW]) + fx;
    float mk = 1.f / (1.f + expf(-g_h3[(b*COFF + 288 + dgi*9 + k)*HWHW + p]));

    float py = dy + (float)h + (float)(k/3 - 1);
    float px = dx + (float)w + (float)(k%3 - 1);
    float y0f = floorf(py), x0f = floorf(px);
    float wy = py - y0f, wx = px - x0f;
    int y0 = (int)y0f, x0 = (int)x0f;

    bool vy0 = (y0 >= 0) && (y0 < HH);
    bool vy1 = (y0+1 >= 0) && (y0+1 < HH);
    bool vx0 = (x0 >= 0) && (x0 < WW);
    bool vx1 = (x0+1 >= 0) && (x0+1 < WW);
    int y0c = min(max(y0, 0), HH-1),  y1c = min(max(y0+1, 0), HH-1);
    int x0c = min(max(x0, 0), WW-1),  x1c = min(max(x0+1, 0), WW-1);
    float m00 = (vy0 && vx0) ? (1.f-wy)*(1.f-wx) : 0.f;
    float m01 = (vy0 && vx1) ? (1.f-wy)*wx       : 0.f;
    float m10 = (vy1 && vx0) ? wy*(1.f-wx)       : 0.f;
    float m11 = (vy1 && vx1) ? wy*wx             : 0.f;
    int i00 = y0c*WW + x0c, i01 = y0c*WW + x1c;
    int i10 = y1c*WW + x0c, i11 = y1c*WW + x1c;

    long pix = (long)(b*HH + h)*WW + w;
    #pragma unroll
    for (int cg = 0; cg < 8; cg++) {
        const float* xp = x + (long)(b*CC + dgi*8 + cg)*HWHW;
        float v = (m00*xp[i00] + m01*xp[i01] + m10*xp[i10] + m11*xp[i11]) * mk;
        bf16 hi, lo; split_bf16(v, hi, lo);
        long di = pix*KFIN + (dgi*8 + cg)*9 + k;
        g_val_hi[di] = hi; g_val_lo[di] = lo;
    }
}

// ---------------- pipelined mma.sync conv/GEMM kernel ----------------
// CTA: one pixel row, M=128 oc, N=160 px; 8 warps 2x4; warp tile 64x40.
// bf16 hi/lo 3-term (AhBh + AhBl + AlBh). cp.async double-buffered.
template<int KC, int TAPS, int EPI>
__global__ void __launch_bounds__(256, 1)
mma_conv_k(const bf16* __restrict__ wHi, const bf16* __restrict__ wLo,
           const bf16* __restrict__ bHi, const bf16* __restrict__ bLo,
           const float* __restrict__ bias,
           float* __restrict__ outF, bf16* __restrict__ outHi, bf16* __restrict__ outLo,
           int CINP, int MT, int COUT)
{
    constexpr bool HALO = (TAPS == 9);
    // A region: per tap per prec = 128 rows * KC*2 bytes
    constexpr int A_PP   = 128 * KC * 2;                 // 4096 / 16384
    constexpr int A_TAPSZ = 2 * A_PP;                    // both precisions
    constexpr int A_REG  = TAPS * A_TAPSZ;               // 73728 / 32768
    constexpr int BROWS  = HALO ? 3*PW162 : WW;          // 486 / 160
    // B region per prec: KC16 -> 2 planes of ceil(486/8)*128 ; KC64 -> rows*128
    constexpr int B_PLANE = (KC == 16) ? (((BROWS + 7)/8)*128) : 0;   // 7808
    constexpr int B_PP    = (KC == 16) ? (2*B_PLANE) : (BROWS*128);   // 15616 / 20480
    constexpr int OFF_B   = A_REG;
    constexpr int CHUNK   = A_REG + 2*B_PP;              // 104960 / 73728
    constexpr int AGRAN   = TAPS * 2 * 128 * (KC/8);     // 4608 / 2048
    constexpr int BGRAN   = 2 * BROWS * (KC/8);          // 1944 / 2560

    extern __shared__ __align__(128) char sm[];
    const uint32_t sb = smem_u32(sm);

    const int tid  = threadIdx.x;
    const int wid  = tid >> 5;
    const int lane = tid & 31;
    const int wm   = wid & 1;
    const int wn   = wid >> 1;
    const int la7  = lane & 7;
    const int hseg = lane >> 4;            // A granule half
    const int pl4  = (lane >> 3) & 1;      // B granule half (ldsm4/2)
    const int rowin4 = la7 + (hseg << 3);  // B ldsm4 row-in-frag

    const int h  = blockIdx.x;
    const int b  = blockIdx.z / MT;
    const int mt = blockIdx.z % MT;
    const int NCH = CINP / KC;

    float acc[20][4];
    #pragma unroll
    for (int i = 0; i < 20; i++)
        #pragma unroll
        for (int j = 0; j < 4; j++) acc[i][j] = 0.f;

    // precomputed A-fragment lane offsets
    uint32_t laneA[4];
    #pragma unroll
    for (int mf = 0; mf < 4; mf++) {
        int row = wm*64 + mf*16 + (lane & 15);
        if (KC == 16)
            laneA[mf] = hseg*2048 + ((row >> 3) << 7) + ((la7 ^ ((row >> 3) & 7)) << 4);
        else
            laneA[mf] = row * 128;   // granule xor applied per-ks
    }

    // ---- staging ----
    auto stage = [&](int buf, int ch) {
        const int cc = ch * KC;
        const uint32_t sbuf = sb + buf*CHUNK;
        #pragma unroll 1
        for (int i = tid; i < AGRAN; i += 256) {
            uint32_t d; const bf16* s;
            if (KC == 16) {
                int m  = i & 127;
                int r  = i >> 7;
                int p  = r & 1;
                int pr = (r >> 1) & 1;
                int t  = r >> 2;
                d = sbuf + t*A_TAPSZ + pr*A_PP + p*2048
                    + ((m >> 3) << 7) + ((((m & 7)) ^ ((m >> 3) & 7)) << 4);
                s = (pr ? wLo : wHi) + ((long)(t*MT + mt)*128 + m)*CINP + cc + p*8;
            } else {
                int g  = i & 7;
                int m  = (i >> 3) & 127;
                int pr = i >> 10;
                d = sbuf + pr*A_PP + m*128 + ((g ^ (m & 7)) << 4);
                s = (pr ? wLo : wHi) + ((long)(mt*128 + m))*CINP + cc + g*8;
            }
            CP16(d, s);
        }
        #pragma unroll 1
        for (int i = tid; i < BGRAN; i += 256) {
            uint32_t d; const bf16* s;
            if (KC == 16) {
                int rw = i % BROWS;
                int q  = i / BROWS;
                int p  = q & 1;
                int pr = q >> 1;
                d = sbuf + OFF_B + pr*B_PP + p*B_PLANE
                    + ((rw >> 3) << 7) + ((((rw & 7)) ^ ((rw >> 3) & 7)) << 4);
                int ky = rw / PW162;
                int pw = rw - ky*PW162;
                s = (pr ? bLo : bHi) + ((long)((b*PH98 + h + ky)*PW162 + pw))*CINP + cc + p*8;
            } else {
                int g  = i & 7;
                int t3 = i >> 3;
                int pr = (t3 >= BROWS) ? 1 : 0;
                int rw = t3 - pr*BROWS;
                d = sbuf + OFF_B + pr*B_PP + rw*128 + ((g ^ (rw & 7)) << 4);
                s = (pr ? bLo : bHi) + ((long)((b*HH + h)*WW + rw))*CINP + cc + g*8;
            }
            CP16(d, s);
        }
    };

    stage(0, 0);
    CPCOMMIT();

    int buf = 0;
    for (int ch = 0; ch < NCH; ch++) {
        if (ch + 1 < NCH) {
            stage(buf ^ 1, ch + 1);
            CPCOMMIT();
            CPWAIT1();
        } else {
            CPWAIT0();
        }
        __syncthreads();

        const uint32_t sbuf = sb + buf*CHUNK;
        #pragma unroll 1
        for (int tap = 0; tap < TAPS; tap++) {
            const int ky = tap / 3, kx = tap - 3*(tap/3);
            const uint32_t atap = sbuf + tap*A_TAPSZ;
            #pragma unroll 1
            for (int ks = 0; ks < KC/16; ks++) {
                uint32_t ah[4][4], al[4][4], bh[5][2], bl[5][2];
                // A fragments
                #pragma unroll
                for (int mf = 0; mf < 4; mf++) {
                    if (KC == 16) {
                        ldsm4(ah[mf], atap + laneA[mf]);
                        ldsm4(al[mf], atap + A_PP + laneA[mf]);
                    } else {
                        uint32_t xo = (uint32_t)(((2*ks + hseg) ^ la7) << 4);
                        ldsm4(ah[mf], atap + laneA[mf] + xo);
                        ldsm4(al[mf], atap + A_PP + laneA[mf] + xo);
                    }
                }
                // B fragments
                if (KC == 16) {
                    int rb = ky*PW162 + wn*40 + kx;
                    #pragma unroll
                    for (int pr = 0; pr < 2; pr++) {
                        uint32_t bbase = sbuf + OFF_B + pr*B_PP + pl4*B_PLANE;
                        uint32_t (*bf)[2] = pr ? bl : bh;
                        #pragma unroll
                        for (int pg = 0; pg < 2; pg++) {
                            int rw = rb + pg*16 + rowin4;
                            uint32_t ad = bbase + ((rw >> 3) << 7)
                                        + ((((rw & 7)) ^ ((rw >> 3) & 7)) << 4);
                            ldsm4(&bf[pg*2][0], ad);
                        }
                        {
                            int rw = rb + 32 + la7;
                            uint32_t ad = bbase + ((rw >> 3) << 7)
                                        + ((((rw & 7)) ^ ((rw >> 3) & 7)) << 4);
                            ldsm2(&bf[4][0], ad);
                        }
                    }
                } else {
                    #pragma unroll
                    for (int pr = 0; pr < 2; pr++) {
                        uint32_t bbase = sbuf + OFF_B + pr*B_PP;
                        uint32_t (*bf)[2] = pr ? bl : bh;
                        #pragma unroll
                        for (int pg = 0; pg < 2; pg++) {
                            int rw = wn*40 + pg*16 + rowin4;
                            uint32_t ad = bbase + rw*128 + (((2*ks + pl4) ^ la7) << 4);
                            ldsm4(&bf[pg*2][0], ad);
                        }
                        {
                            int rw = wn*40 + 32 + la7;
                            uint32_t ad = bbase + rw*128 + (((2*ks + pl4) ^ la7) << 4);
                            ldsm2(&bf[4][0], ad);
                        }
                    }
                }
                // 3-term MMA
                #pragma unroll
                for (int n = 0; n < 5; n++)
                    #pragma unroll
                    for (int m = 0; m < 4; m++)
                        mma_bf16(acc[m*5+n], ah[m], bh[n]);
                #pragma unroll
                for (int n = 0; n < 5; n++)
                    #pragma unroll
                    for (int m = 0; m < 4; m++)
                        mma_bf16(acc[m*5+n], ah[m], bl[n]);
                #pragma unroll
                for (int n = 0; n < 5; n++)
                    #pragma unroll
                    for (int m = 0; m < 4; m++)
                        mma_bf16(acc[m*5+n], al[m], bh[n]);
            }
        }
        __syncthreads();
        buf ^= 1;
    }

    // ---- epilogue ----
    #pragma unroll
    for (int m = 0; m < 4; m++) {
        #pragma unroll
        for (int half = 0; half < 2; half++) {
            int ml = wm*64 + m*16 + (lane >> 2) + half*8;
            int oc = mt*128 + ml;
            if (oc >= COUT) continue;
            float bz = bias[oc];
            #pragma unroll
            for (int n = 0; n < 5; n++) {
                int nn = wn*40 + n*8 + (lane & 3)*2;
                float v0 = acc[m*5+n][half*2+0] + bz;
                float v1 = acc[m*5+n][half*2+1] + bz;
                if (EPI == 0) {
                    v0 = (v0 >= 0.f) ? v0 : 0.1f*v0;
                    v1 = (v1 >= 0.f) ? v1 : 0.1f*v1;
                    long d0 = ((long)(b*PH98 + h + 1)*PW162 + 1 + nn)*CC + ml;
                    bf16 h0, l0, h1, l1;
                    split_bf16(v0, h0, l0); split_bf16(v1, h1, l1);
                    outHi[d0] = h0;      outLo[d0] = l0;
                    outHi[d0 + CC] = h1; outLo[d0 + CC] = l1;
                } else {
                    float2 o; o.x = v0; o.y = v1;
                    *(float2*)(outF + ((long)(b*COUT + oc)*HH + h)*WW + nn) = o;
                }
            }
        }
    }
}

// ---------------- launcher ----------------
#define SMEM_HALO (2*(9*2*4096 + 2*15616))      // 209920
#define SMEM_1x1  (2*(2*16384 + 2*20480))       // 147456

extern "C" void kernel_launch(void* const* d_in, const int* in_sizes, int n_in,
                              void* d_out, int out_size)
{
    const float* x    = (const float*)d_in[0];
    const float* exf  = (const float*)d_in[1];
    const float* f1   = (const float*)d_in[2];
    const float* f2   = (const float*)d_in[3];
    const float* wgt  = (const float*)d_in[4];
    const float* bias = (const float*)d_in[5];
    const float* cw0  = (const float*)d_in[6];
    const float* cb0  = (const float*)d_in[7];
    const float* cw1  = (const float*)d_in[8];
    const float* cb1  = (const float*)d_in[9];
    const float* cw2  = (const float*)d_in[10];
    const float* cb2  = (const float*)d_in[11];
    const float* cw3  = (const float*)d_in[12];
    const float* cb3  = (const float*)d_in[13];
    float* out = (float*)d_out;

    cudaFuncSetAttribute(mma_conv_k<16,9,0>, cudaFuncAttributeMaxDynamicSharedMemorySize, SMEM_HALO);
    cudaFuncSetAttribute(mma_conv_k<16,9,1>, cudaFuncAttributeMaxDynamicSharedMemorySize, SMEM_HALO);
    cudaFuncSetAttribute(mma_conv_k<64,1,1>, cudaFuncAttributeMaxDynamicSharedMemorySize, SMEM_1x1);

    void *pefh, *pefl, *pAh, *pAl, *pBh, *pBl, *ph3, *pvh, *pvl;
    void *pw0h, *pw0l, *pw1h, *pw1l, *pw2h, *pw2l, *pw3h, *pw3l, *pwfh, *pwfl;
    cudaGetSymbolAddress(&pefh, g_ef_hi);  cudaGetSymbolAddress(&pefl, g_ef_lo);
    cudaGetSymbolAddress(&pAh, g_bA_hi);   cudaGetSymbolAddress(&pAl, g_bA_lo);
    cudaGetSymbolAddress(&pBh, g_bB_hi);   cudaGetSymbolAddress(&pBl, g_bB_lo);
    cudaGetSymbolAddress(&ph3, g_h3);
    cudaGetSymbolAddress(&pvh, g_val_hi);  cudaGetSymbolAddress(&pvl, g_val_lo);
    cudaGetSymbolAddress(&pw0h, g_w0_hi);  cudaGetSymbolAddress(&pw0l, g_w0_lo);
    cudaGetSymbolAddress(&pw1h, g_w1_hi);  cudaGetSymbolAddress(&pw1l, g_w1_lo);
    cudaGetSymbolAddress(&pw2h, g_w2_hi);  cudaGetSymbolAddress(&pw2l, g_w2_lo);
    cudaGetSymbolAddress(&pw3h, g_w3_hi);  cudaGetSymbolAddress(&pw3l, g_w3_lo);
    cudaGetSymbolAddress(&pwfh, g_wf_hi);  cudaGetSymbolAddress(&pwfl, g_wf_lo);

    zero_bufs_k<<<(BB*PH98*PW162*CC + 255)/256, 256>>>();
    pack_ef_k<<<(BB*PH98*PW162*CIN0P + 255)/256, 256>>>(exf, f1, f2);
    wprep_k<<<(9*CC*CIN0P + 255)/256, 256>>>(cw0, (bf16*)pw0h, (bf16*)pw0l, 128, 388, CIN0P, 128);
    wprep_k<<<(9*CC*CC   + 255)/256, 256>>>(cw1, (bf16*)pw1h, (bf16*)pw1l, 128, 128, 128, 128);
    wprep_k<<<(9*CC*CC   + 255)/256, 256>>>(cw2, (bf16*)pw2h, (bf16*)pw2l, 128, 128, 128, 128);
    wprep_k<<<(9*512*CC  + 255)/256, 256>>>(cw3, (bf16*)pw3h, (bf16*)pw3l, COFF, 128, 128, 512);
    wprep_fin_k<<<(CC*KFIN + 255)/256, 256>>>(wgt);

    dim3 g1(HH, 1, BB);
    mma_conv_k<16,9,0><<<g1, 256, SMEM_HALO>>>(
        (const bf16*)pw0h, (const bf16*)pw0l, (const bf16*)pefh, (const bf16*)pefl,
        cb0, nullptr, (bf16*)pAh, (bf16*)pAl, CIN0P, 1, 128);
    mma_conv_k<16,9,0><<<g1, 256, SMEM_HALO>>>(
        (const bf16*)pw1h, (const bf16*)pw1l, (const bf16*)pAh, (const bf16*)pAl,
        cb1, nullptr, (bf16*)pBh, (bf16*)pBl, 128, 1, 128);
    mma_conv_k<16,9,0><<<g1, 256, SMEM_HALO>>>(
        (const bf16*)pw2h, (const bf16*)pw2l, (const bf16*)pBh, (const bf16*)pBl,
        cb2, nullptr, (bf16*)pAh, (bf16*)pAl, 128, 1, 128);

    dim3 g3(HH, 1, BB*4);
    mma_conv_k<16,9,1><<<g3, 256, SMEM_HALO>>>(
        (const bf16*)pw3h, (const bf16*)pw3l, (const bf16*)pAh, (const bf16*)pAl,
        cb3, (float*)ph3, nullptr, nullptr, 128, 4, COFF);

    gather_k<<<(BB*16*9*HWHW + 255)/256, 256>>>(x, f1, f2);

    mma_conv_k<64,1,1><<<g1, 256, SMEM_1x1>>>(
        (const bf16*)pwfh, (const bf16*)pwfl, (const bf16*)pvh, (const bf16*)pvl,
        bias, out, nullptr, nullptr, KFIN, 1, 128);
}

// round 9
// speedup vs baseline: 2.5041x; 1.3835x over previous
#include <cuda_runtime.h>
#include <cuda_bf16.h>
#include <math.h>
#include <stdint.h>

#define BB 2
#define CC 128
#define HH 96
#define WW 160
#define HWHW (HH*WW)
#define PH98 98
#define PW162 162
#define NPIX (BB*HWHW)
#define COFF 432
#define CIN0P 400
#define KFIN 1152

typedef unsigned long long u64;
typedef __nv_bfloat16 bf16;

// ---------------- device-global scratch ----------------
__device__ __align__(16) bf16 g_ef_hi [BB*PH98*PW162*CIN0P];
__device__ __align__(16) bf16 g_ef_lo [BB*PH98*PW162*CIN0P];
__device__ __align__(16) bf16 g_bA_hi [BB*PH98*PW162*CC];
__device__ __align__(16) bf16 g_bA_lo [BB*PH98*PW162*CC];
__device__ __align__(16) bf16 g_bB_hi [BB*PH98*PW162*CC];
__device__ __align__(16) bf16 g_bB_lo [BB*PH98*PW162*CC];
__device__ float g_h3 [BB*COFF*HWHW];
__device__ __align__(16) bf16 g_val_hi[(long)KFIN*NPIX];   // K-major!
__device__ __align__(16) bf16 g_val_lo[(long)KFIN*NPIX];
__device__ __align__(16) bf16 g_w0_hi [9*CC*CIN0P];
__device__ __align__(16) bf16 g_w0_lo [9*CC*CIN0P];
__device__ __align__(16) bf16 g_w1_hi [9*CC*CC];
__device__ __align__(16) bf16 g_w1_lo [9*CC*CC];
__device__ __align__(16) bf16 g_w2_hi [9*CC*CC];
__device__ __align__(16) bf16 g_w2_lo [9*CC*CC];
__device__ __align__(16) bf16 g_w3_hi [9*512*CC];
__device__ __align__(16) bf16 g_w3_lo [9*512*CC];
__device__ __align__(16) bf16 g_wf_hi [CC*KFIN];
__device__ __align__(16) bf16 g_wf_lo [CC*KFIN];

// ---------------- helpers ----------------
__device__ __forceinline__ uint32_t smem_u32(const void* p) {
    uint32_t a;
    asm("{ .reg .u64 t; cvta.to.shared.u64 t, %1; cvt.u32.u64 %0, t; }" : "=r"(a) : "l"(p));
    return a;
}
__device__ __forceinline__ void ldsm4(uint32_t* r, uint32_t a) {
    asm volatile("ldmatrix.sync.aligned.m8n8.x4.shared.b16 {%0,%1,%2,%3}, [%4];"
                 : "=r"(r[0]), "=r"(r[1]), "=r"(r[2]), "=r"(r[3]) : "r"(a));
}
__device__ __forceinline__ void ldsm2(uint32_t* r, uint32_t a) {
    asm volatile("ldmatrix.sync.aligned.m8n8.x2.shared.b16 {%0,%1}, [%2];"
                 : "=r"(r[0]), "=r"(r[1]) : "r"(a));
}
__device__ __forceinline__ void ldsm4t(uint32_t* r, uint32_t a) {
    asm volatile("ldmatrix.sync.aligned.m8n8.x4.trans.shared.b16 {%0,%1,%2,%3}, [%4];"
                 : "=r"(r[0]), "=r"(r[1]), "=r"(r[2]), "=r"(r[3]) : "r"(a));
}
__device__ __forceinline__ void ldsm2t(uint32_t* r, uint32_t a) {
    asm volatile("ldmatrix.sync.aligned.m8n8.x2.trans.shared.b16 {%0,%1}, [%2];"
                 : "=r"(r[0]), "=r"(r[1]) : "r"(a));
}
__device__ __forceinline__ void mma_bf16(float* d, const uint32_t* a, const uint32_t* b) {
    asm volatile("mma.sync.aligned.m16n8k16.row.col.f32.bf16.bf16.f32 "
                 "{%0,%1,%2,%3}, {%4,%5,%6,%7}, {%8,%9}, {%0,%1,%2,%3};"
                 : "+f"(d[0]), "+f"(d[1]), "+f"(d[2]), "+f"(d[3])
                 : "r"(a[0]), "r"(a[1]), "r"(a[2]), "r"(a[3]), "r"(b[0]), "r"(b[1]));
}
__device__ __forceinline__ void split_bf16(float v, bf16& hi, bf16& lo) {
    hi = __float2bfloat16(v);
    lo = __float2bfloat16(v - __bfloat162float(hi));
}
#define CP16(d, s)  asm volatile("cp.async.cg.shared.global [%0], [%1], 16;" :: "r"(d), "l"(s))
#define CPCOMMIT()  asm volatile("cp.async.commit_group;" ::: "memory")
#define CPWAIT0()   asm volatile("cp.async.wait_group 0;" ::: "memory")
#define CPWAIT1()   asm volatile("cp.async.wait_group 1;" ::: "memory")

// ---------------- prep kernels ----------------
__global__ void zero_bufs_k() {
    int i = blockIdx.x * 256 + threadIdx.x;
    if (i >= BB*PH98*PW162*CC) return;
    bf16 z = __float2bfloat16(0.f);
    g_bA_hi[i] = z; g_bA_lo[i] = z; g_bB_hi[i] = z; g_bB_lo[i] = z;
}

__global__ void pack_ef_k(const float* __restrict__ exf, const float* __restrict__ f1,
                          const float* __restrict__ f2) {
    int i = blockIdx.x * 256 + threadIdx.x;
    if (i >= BB*PH98*PW162*CIN0P) return;
    int c  = i % CIN0P;
    int pw = (i / CIN0P) % PW162;
    int ph = (i / (CIN0P*PW162)) % PH98;
    int b  = i / (CIN0P*PW162*PH98);
    float v = 0.f;
    if (ph >= 1 && ph <= HH && pw >= 1 && pw <= WW && c < 388) {
        int p = (ph-1)*WW + (pw-1);
        if (c < 384)      v = exf[(b*384 + c)*HWHW + p];
        else if (c < 386) v = f1[(b*2 + (c-384))*HWHW + p];
        else              v = f2[(b*2 + (c-386))*HWHW + p];
    }
    bf16 hi, lo; split_bf16(v, hi, lo);
    g_ef_hi[i] = hi; g_ef_lo[i] = lo;
}

__global__ void wprep_k(const float* __restrict__ src, bf16* __restrict__ dHi,
                        bf16* __restrict__ dLo, int COUT, int CIN, int CINP, int COUTP) {
    int i = blockIdx.x * 256 + threadIdx.x;
    if (i >= 9*COUTP*CINP) return;
    int ci  = i % CINP;
    int oc  = (i / CINP) % COUTP;
    int tap = i / (CINP*COUTP);
    float v = (oc < COUT && ci < CIN) ? src[((long)oc*CIN + ci)*9 + tap] : 0.f;
    bf16 hi, lo; split_bf16(v, hi, lo);
    dHi[i] = hi; dLo[i] = lo;
}

__global__ void wprep_fin_k(const float* __restrict__ src) {
    int i = blockIdx.x * 256 + threadIdx.x;
    if (i >= CC*KFIN) return;
    int k  = i % KFIN;
    int oc = i / KFIN;
    int ci = k / 9, tap = k % 9;
    float v = src[((long)oc*CC + ci)*9 + tap];
    bf16 hi, lo; split_bf16(v, hi, lo);
    g_wf_hi[i] = hi; g_wf_lo[i] = lo;
}

// ---------------- deform gather (K-major coalesced stores) ----------------
__global__ void gather_k(const float* __restrict__ x, const float* __restrict__ f1,
                         const float* __restrict__ f2) {
    int idx = blockIdx.x * 256 + threadIdx.x;
    if (idx >= BB*16*9*HWHW) return;
    int w = idx % WW;   int t = idx / WW;
    int h = t % HH;     t /= HH;
    int k = t % 9;      t /= 9;
    int dgi = t % 16;
    int b   = t / 16;

    int p = h*WW + w;
    const float* fl = (dgi < 8) ? f1 : f2;
    float fy = fl[(b*2 + 1)*HWHW + p];
    float fx = fl[(b*2 + 0)*HWHW + p];

    int coff = (b*COFF + dgi*18 + k*2)*HWHW + p;
    float dy = 10.f * tanhf(g_h3[coff])        + fy;
    float dx = 10.f * tanhf(g_h3[coff + HWHW]) + fx;
    float mk = 1.f / (1.f + expf(-g_h3[(b*COFF + 288 + dgi*9 + k)*HWHW + p]));

    float py = dy + (float)h + (float)(k/3 - 1);
    float px = dx + (float)w + (float)(k%3 - 1);
    float y0f = floorf(py), x0f = floorf(px);
    float wy = py - y0f, wx = px - x0f;
    int y0 = (int)y0f, x0 = (int)x0f;

    bool vy0 = (y0 >= 0) && (y0 < HH);
    bool vy1 = (y0+1 >= 0) && (y0+1 < HH);
    bool vx0 = (x0 >= 0) && (x0 < WW);
    bool vx1 = (x0+1 >= 0) && (x0+1 < WW);
    int y0c = min(max(y0, 0), HH-1),  y1c = min(max(y0+1, 0), HH-1);
    int x0c = min(max(x0, 0), WW-1),  x1c = min(max(x0+1, 0), WW-1);
    float m00 = (vy0 && vx0) ? (1.f-wy)*(1.f-wx) : 0.f;
    float m01 = (vy0 && vx1) ? (1.f-wy)*wx       : 0.f;
    float m10 = (vy1 && vx0) ? wy*(1.f-wx)       : 0.f;
    float m11 = (vy1 && vx1) ? wy*wx             : 0.f;
    int i00 = y0c*WW + x0c, i01 = y0c*WW + x1c;
    int i10 = y1c*WW + x0c, i11 = y1c*WW + x1c;

    long pix = (long)b*HWHW + p;
    #pragma unroll
    for (int cg = 0; cg < 8; cg++) {
        const float* xp = x + (long)(b*CC + dgi*8 + cg)*HWHW;
        float v = (m00*xp[i00] + m01*xp[i01] + m10*xp[i10] + m11*xp[i11]) * mk;
        bf16 hi, lo; split_bf16(v, hi, lo);
        long di = (long)((dgi*8 + cg)*9 + k)*NPIX + pix;
        g_val_hi[di] = hi; g_val_lo[di] = lo;
    }
}

// ---------------- pipelined mma.sync 3x3 conv kernel ----------------
// CTA: one pixel row, M=128 oc, N=160 px; 8 warps 2x4; warp tile 64x40.
// bf16 hi/lo 3-term (AhBh + AhBl + AlBh). cp.async double-buffered.
template<int EPI>
__global__ void __launch_bounds__(256, 1)
mma_conv_k(const bf16* __restrict__ wHi, const bf16* __restrict__ wLo,
           const bf16* __restrict__ bHi, const bf16* __restrict__ bLo,
           const float* __restrict__ bias,
           float* __restrict__ outF, bf16* __restrict__ outHi, bf16* __restrict__ outLo,
           int CINP, int MT, int COUT)
{
    constexpr int KC = 16, TAPS = 9;
    constexpr int A_PP   = 128 * KC * 2;                 // 4096
    constexpr int A_TAPSZ = 2 * A_PP;
    constexpr int A_REG  = TAPS * A_TAPSZ;               // 73728
    constexpr int BROWS  = 3*PW162;                      // 486
    constexpr int B_PLANE = ((BROWS + 7)/8)*128;         // 7808
    constexpr int B_PP    = 2*B_PLANE;                   // 15616
    constexpr int OFF_B   = A_REG;
    constexpr int CHUNK   = A_REG + 2*B_PP;              // 104960
    constexpr int AGRAN   = TAPS * 2 * 128 * (KC/8);     // 4608
    constexpr int BGRAN   = 2 * BROWS * (KC/8);          // 1944

    extern __shared__ __align__(128) char sm[];
    const uint32_t sb = smem_u32(sm);

    const int tid  = threadIdx.x;
    const int wid  = tid >> 5;
    const int lane = tid & 31;
    const int wm   = wid & 1;
    const int wn   = wid >> 1;
    const int la7  = lane & 7;
    const int hseg = lane >> 4;
    const int pl4  = (lane >> 3) & 1;
    const int rowin4 = la7 + (hseg << 3);

    const int h  = blockIdx.x;
    const int b  = blockIdx.z / MT;
    const int mt = blockIdx.z % MT;
    const int NCH = CINP / KC;

    float acc[20][4];
    #pragma unroll
    for (int i = 0; i < 20; i++)
        #pragma unroll
        for (int j = 0; j < 4; j++) acc[i][j] = 0.f;

    uint32_t laneA[4];
    #pragma unroll
    for (int mf = 0; mf < 4; mf++) {
        int row = wm*64 + mf*16 + (lane & 15);
        laneA[mf] = hseg*2048 + ((row >> 3) << 7) + ((la7 ^ ((row >> 3) & 7)) << 4);
    }

    auto stage = [&](int buf, int ch) {
        const int cc = ch * KC;
        const uint32_t sbuf = sb + buf*CHUNK;
        #pragma unroll 1
        for (int i = tid; i < AGRAN; i += 256) {
            int m  = i & 127;
            int r  = i >> 7;
            int p  = r & 1;
            int pr = (r >> 1) & 1;
            int t  = r >> 2;
            uint32_t d = sbuf + t*A_TAPSZ + pr*A_PP + p*2048
                + ((m >> 3) << 7) + ((((m & 7)) ^ ((m >> 3) & 7)) << 4);
            const bf16* s = (pr ? wLo : wHi) + ((long)(t*MT + mt)*128 + m)*CINP + cc + p*8;
            CP16(d, s);
        }
        #pragma unroll 1
        for (int i = tid; i < BGRAN; i += 256) {
            int rw = i % BROWS;
            int q  = i / BROWS;
            int p  = q & 1;
            int pr = q >> 1;
            uint32_t d = sbuf + OFF_B + pr*B_PP + p*B_PLANE
                + ((rw >> 3) << 7) + ((((rw & 7)) ^ ((rw >> 3) & 7)) << 4);
            int ky = rw / PW162;
            int pw = rw - ky*PW162;
            const bf16* s = (pr ? bLo : bHi) + ((long)((b*PH98 + h + ky)*PW162 + pw))*CINP + cc + p*8;
            CP16(d, s);
        }
    };

    stage(0, 0);
    CPCOMMIT();

    int buf = 0;
    for (int ch = 0; ch < NCH; ch++) {
        if (ch + 1 < NCH) { stage(buf ^ 1, ch + 1); CPCOMMIT(); CPWAIT1(); }
        else              { CPWAIT0(); }
        __syncthreads();

        const uint32_t sbuf = sb + buf*CHUNK;
        #pragma unroll 1
        for (int tap = 0; tap < TAPS; tap++) {
            const int ky = tap / 3, kx = tap - 3*(tap/3);
            const uint32_t atap = sbuf + tap*A_TAPSZ;
            uint32_t ah[4][4], al[4][4], bh[5][2], bl[5][2];
            #pragma unroll
            for (int mf = 0; mf < 4; mf++) {
                ldsm4(ah[mf], atap + laneA[mf]);
                ldsm4(al[mf], atap + A_PP + laneA[mf]);
            }
            int rb = ky*PW162 + wn*40 + kx;
            #pragma unroll
            for (int pr = 0; pr < 2; pr++) {
                uint32_t bbase = sbuf + OFF_B + pr*B_PP + pl4*B_PLANE;
                uint32_t (*bf)[2] = pr ? bl : bh;
                #pragma unroll
                for (int pg = 0; pg < 2; pg++) {
                    int rw = rb + pg*16 + rowin4;
                    uint32_t ad = bbase + ((rw >> 3) << 7)
                                + ((((rw & 7)) ^ ((rw >> 3) & 7)) << 4);
                    ldsm4(&bf[pg*2][0], ad);
                }
                {
                    int rw = rb + 32 + la7;
                    uint32_t ad = bbase + ((rw >> 3) << 7)
                                + ((((rw & 7)) ^ ((rw >> 3) & 7)) << 4);
                    ldsm2(&bf[4][0], ad);
                }
            }
            #pragma unroll
            for (int n = 0; n < 5; n++)
                #pragma unroll
                for (int m = 0; m < 4; m++)
                    mma_bf16(acc[m*5+n], ah[m], bh[n]);
            #pragma unroll
            for (int n = 0; n < 5; n++)
                #pragma unroll
                for (int m = 0; m < 4; m++)
                    mma_bf16(acc[m*5+n], ah[m], bl[n]);
            #pragma unroll
            for (int n = 0; n < 5; n++)
                #pragma unroll
                for (int m = 0; m < 4; m++)
                    mma_bf16(acc[m*5+n], al[m], bh[n]);
        }
        __syncthreads();
        buf ^= 1;
    }

    #pragma unroll
    for (int m = 0; m < 4; m++) {
        #pragma unroll
        for (int half = 0; half < 2; half++) {
            int ml = wm*64 + m*16 + (lane >> 2) + half*8;
            int oc = mt*128 + ml;
            if (oc >= COUT) continue;
            float bz = bias[oc];
            #pragma unroll
            for (int n = 0; n < 5; n++) {
                int nn = wn*40 + n*8 + (lane & 3)*2;
                float v0 = acc[m*5+n][half*2+0] + bz;
                float v1 = acc[m*5+n][half*2+1] + bz;
                if (EPI == 0) {
                    v0 = (v0 >= 0.f) ? v0 : 0.1f*v0;
                    v1 = (v1 >= 0.f) ? v1 : 0.1f*v1;
                    long d0 = ((long)(b*PH98 + h + 1)*PW162 + 1 + nn)*CC + ml;
                    bf16 h0, l0, h1, l1;
                    split_bf16(v0, h0, l0); split_bf16(v1, h1, l1);
                    outHi[d0] = h0;      outLo[d0] = l0;
                    outHi[d0 + CC] = h1; outLo[d0 + CC] = l1;
                } else {
                    float2 o; o.x = v0; o.y = v1;
                    *(float2*)(outF + ((long)(b*COUT + oc)*HH + h)*WW + nn) = o;
                }
            }
        }
    }
}

// ---------------- final GEMM: out = Wf * val, K=1152, K-major B ----------
__global__ void __launch_bounds__(256, 1)
mma_gemm_k(const bf16* __restrict__ wHi, const bf16* __restrict__ wLo,
           const bf16* __restrict__ vHi, const bf16* __restrict__ vLo,
           const float* __restrict__ bias, float* __restrict__ outF)
{
    constexpr int KC = 64;
    constexpr int A_PP  = 128 * KC * 2;                  // 16384
    constexpr int A_REG = 2 * A_PP;                      // 32768
    constexpr int BSTR  = 336;                           // padded row (160*2 + 16)
    constexpr int B_PP  = KC * BSTR;                     // 21504
    constexpr int OFF_B = A_REG;
    constexpr int CHUNK = A_REG + 2*B_PP;                // 75776
    constexpr int AGRAN = 2 * 128 * (KC/8);              // 2048
    constexpr int BGRAN = 2 * KC * 20;                   // 2560

    extern __shared__ __align__(128) char sm[];
    const uint32_t sb = smem_u32(sm);

    const int tid  = threadIdx.x;
    const int wid  = tid >> 5;
    const int lane = tid & 31;
    const int wm   = wid & 1;
    const int wn   = wid >> 1;
    const int la7  = lane & 7;
    const int hseg = lane >> 4;

    const int h = blockIdx.x;
    const int b = blockIdx.z;
    const long rowpix = (long)b*HWHW + h*WW;   // 160 contiguous pixels
    constexpr int NCH = KFIN / KC;             // 18

    float acc[20][4];
    #pragma unroll
    for (int i = 0; i < 20; i++)
        #pragma unroll
        for (int j = 0; j < 4; j++) acc[i][j] = 0.f;

    uint32_t laneA[4];
    #pragma unroll
    for (int mf = 0; mf < 4; mf++) {
        int row = wm*64 + mf*16 + (lane & 15);
        laneA[mf] = row * 128;
    }
    // B trans-ldmatrix lane addresses (within a k16 x n-group frame)
    const int bg = lane >> 3;                       // group 0..3
    const int bk4 = (bg & 1)*8 + la7;               // k-in-16
    const int bn4 = (bg >> 1)*8;                    // n offset 0/8
    const int bk2 = ((lane >> 3) & 1)*8 + la7;      // x2: lanes 0..15

    auto stage = [&](int buf, int ch) {
        const int cc = ch * KC;
        const uint32_t sbuf = sb + buf*CHUNK;
        #pragma unroll 1
        for (int i = tid; i < AGRAN; i += 256) {
            int g  = i & 7;
            int m  = (i >> 3) & 127;
            int pr = i >> 10;
            uint32_t d = sbuf + pr*A_PP + m*128 + ((g ^ (m & 7)) << 4);
            const bf16* s = (pr ? wLo : wHi) + (long)m*KFIN + cc + g*8;
            CP16(d, s);
        }
        #pragma unroll 1
        for (int i = tid; i < BGRAN; i += 256) {
            int g  = i % 20;
            int t2 = i / 20;
            int pr = (t2 >= KC) ? 1 : 0;
            int rw = t2 - pr*KC;
            uint32_t d = sbuf + OFF_B + pr*B_PP + rw*BSTR + g*16;
            const bf16* s = (pr ? vLo : vHi) + (long)(cc + rw)*NPIX + rowpix + g*8;
            CP16(d, s);
        }
    };

    stage(0, 0);
    CPCOMMIT();

    int buf = 0;
    for (int ch = 0; ch < NCH; ch++) {
        if (ch + 1 < NCH) { stage(buf ^ 1, ch + 1); CPCOMMIT(); CPWAIT1(); }
        else              { CPWAIT0(); }
        __syncthreads();

        const uint32_t sbuf = sb + buf*CHUNK;
        #pragma unroll 1
        for (int ks = 0; ks < KC/16; ks++) {
            uint32_t ah[4][4], al[4][4], bh[5][2], bl[5][2];
            #pragma unroll
            for (int mf = 0; mf < 4; mf++) {
                uint32_t xo = (uint32_t)(((2*ks + hseg) ^ la7) << 4);
                ldsm4(ah[mf], sbuf + laneA[mf] + xo);
                ldsm4(al[mf], sbuf + A_PP + laneA[mf] + xo);
            }
            #pragma unroll
            for (int pr = 0; pr < 2; pr++) {
                uint32_t bbase = sbuf + OFF_B + pr*B_PP + (ks*16)*BSTR;
                uint32_t (*bf)[2] = pr ? bl : bh;
                // n tiles 0,1
                ldsm4t(&bf[0][0], bbase + bk4*BSTR + (wn*40 + bn4)*2);
                // n tiles 2,3
                ldsm4t(&bf[2][0], bbase + bk4*BSTR + (wn*40 + 16 + bn4)*2);
                // n tile 4
                ldsm2t(&bf[4][0], bbase + bk2*BSTR + (wn*40 + 32)*2);
            }
            #pragma unroll
            for (int n = 0; n < 5; n++)
                #pragma unroll
                for (int m = 0; m < 4; m++)
                    mma_bf16(acc[m*5+n], ah[m], bh[n]);
            #pragma unroll
            for (int n = 0; n < 5; n++)
                #pragma unroll
                for (int m = 0; m < 4; m++)
                    mma_bf16(acc[m*5+n], ah[m], bl[n]);
            #pragma unroll
            for (int n = 0; n < 5; n++)
                #pragma unroll
                for (int m = 0; m < 4; m++)
                    mma_bf16(acc[m*5+n], al[m], bh[n]);
        }
        __syncthreads();
        buf ^= 1;
    }

    #pragma unroll
    for (int m = 0; m < 4; m++) {
        #pragma unroll
        for (int half = 0; half < 2; half++) {
            int oc = wm*64 + m*16 + (lane >> 2) + half*8;
            float bz = bias[oc];
            #pragma unroll
            for (int n = 0; n < 5; n++) {
                int nn = wn*40 + n*8 + (lane & 3)*2;
                float2 o;
                o.x = acc[m*5+n][half*2+0] + bz;
                o.y = acc[m*5+n][half*2+1] + bz;
                *(float2*)(outF + ((long)(b*CC + oc)*HH + h)*WW + nn) = o;
            }
        }
    }
}

// ---------------- launcher ----------------
#define SMEM_HALO (2*(9*2*4096 + 2*15616))      // 209920
#define SMEM_GEMM (2*(2*16384 + 2*21504))       // 151552

extern "C" void kernel_launch(void* const* d_in, const int* in_sizes, int n_in,
                              void* d_out, int out_size)
{
    const float* x    = (const float*)d_in[0];
    const float* exf  = (const float*)d_in[1];
    const float* f1   = (const float*)d_in[2];
    const float* f2   = (const float*)d_in[3];
    const float* wgt  = (const float*)d_in[4];
    const float* bias = (const float*)d_in[5];
    const float* cw0  = (const float*)d_in[6];
    const float* cb0  = (const float*)d_in[7];
    const float* cw1  = (const float*)d_in[8];
    const float* cb1  = (const float*)d_in[9];
    const float* cw2  = (const float*)d_in[10];
    const float* cb2  = (const float*)d_in[11];
    const float* cw3  = (const float*)d_in[12];
    const float* cb3  = (const float*)d_in[13];
    float* out = (float*)d_out;

    cudaFuncSetAttribute(mma_conv_k<0>, cudaFuncAttributeMaxDynamicSharedMemorySize, SMEM_HALO);
    cudaFuncSetAttribute(mma_conv_k<1>, cudaFuncAttributeMaxDynamicSharedMemorySize, SMEM_HALO);
    cudaFuncSetAttribute(mma_gemm_k,    cudaFuncAttributeMaxDynamicSharedMemorySize, SMEM_GEMM);

    void *pefh, *pefl, *pAh, *pAl, *pBh, *pBl, *ph3, *pvh, *pvl;
    void *pw0h, *pw0l, *pw1h, *pw1l, *pw2h, *pw2l, *pw3h, *pw3l, *pwfh, *pwfl;
    cudaGetSymbolAddress(&pefh, g_ef_hi);  cudaGetSymbolAddress(&pefl, g_ef_lo);
    cudaGetSymbolAddress(&pAh, g_bA_hi);   cudaGetSymbolAddress(&pAl, g_bA_lo);
    cudaGetSymbolAddress(&pBh, g_bB_hi);   cudaGetSymbolAddress(&pBl, g_bB_lo);
    cudaGetSymbolAddress(&ph3, g_h3);
    cudaGetSymbolAddress(&pvh, g_val_hi);  cudaGetSymbolAddress(&pvl, g_val_lo);
    cudaGetSymbolAddress(&pw0h, g_w0_hi);  cudaGetSymbolAddress(&pw0l, g_w0_lo);
    cudaGetSymbolAddress(&pw1h, g_w1_hi);  cudaGetSymbolAddress(&pw1l, g_w1_lo);
    cudaGetSymbolAddress(&pw2h, g_w2_hi);  cudaGetSymbolAddress(&pw2l, g_w2_lo);
    cudaGetSymbolAddress(&pw3h, g_w3_hi);  cudaGetSymbolAddress(&pw3l, g_w3_lo);
    cudaGetSymbolAddress(&pwfh, g_wf_hi);  cudaGetSymbolAddress(&pwfl, g_wf_lo);

    // launches 1-5 (ncu -s 5 profiles launch 6 = conv0)
    zero_bufs_k<<<(BB*PH98*PW162*CC + 255)/256, 256>>>();
    pack_ef_k<<<(BB*PH98*PW162*CIN0P + 255)/256, 256>>>(exf, f1, f2);
    wprep_k<<<(9*CC*CIN0P + 255)/256, 256>>>(cw0, (bf16*)pw0h, (bf16*)pw0l, 128, 388, CIN0P, 128);
    wprep_k<<<(9*CC*CC   + 255)/256, 256>>>(cw1, (bf16*)pw1h, (bf16*)pw1l, 128, 128, 128, 128);
    wprep_k<<<(9*CC*CC   + 255)/256, 256>>>(cw2, (bf16*)pw2h, (bf16*)pw2l, 128, 128, 128, 128);

    dim3 g1(HH, 1, BB);
    mma_conv_k<0><<<g1, 256, SMEM_HALO>>>(                      // launch 6: profiled
        (const bf16*)pw0h, (const bf16*)pw0l, (const bf16*)pefh, (const bf16*)pefl,
        cb0, nullptr, (bf16*)pAh, (bf16*)pAl, CIN0P, 1, 128);

    wprep_k<<<(9*512*CC  + 255)/256, 256>>>(cw3, (bf16*)pw3h, (bf16*)pw3l, COFF, 128, 128, 512);
    wprep_fin_k<<<(CC*KFIN + 255)/256, 256>>>(wgt);

    mma_conv_k<0><<<g1, 256, SMEM_HALO>>>(
        (const bf16*)pw1h, (const bf16*)pw1l, (const bf16*)pAh, (const bf16*)pAl,
        cb1, nullptr, (bf16*)pBh, (bf16*)pBl, 128, 1, 128);
    mma_conv_k<0><<<g1, 256, SMEM_HALO>>>(
        (const bf16*)pw2h, (const bf16*)pw2l, (const bf16*)pBh, (const bf16*)pBl,
        cb2, nullptr, (bf16*)pAh, (bf16*)pAl, 128, 1, 128);

    dim3 g3(HH, 1, BB*4);
    mma_conv_k<1><<<g3, 256, SMEM_HALO>>>(
        (const bf16*)pw3h, (const bf16*)pw3l, (const bf16*)pAh, (const bf16*)pAl,
        cb3, (float*)ph3, nullptr, nullptr, 128, 4, COFF);

    gather_k<<<(BB*16*9*HWHW + 255)/256, 256>>>(x, f1, f2);

    mma_gemm_k<<<g1, 256, SMEM_GEMM>>>(
        (const bf16*)pwfh, (const bf16*)pwfl, (const bf16*)pvh, (const bf16*)pvl,
        bias, out);
}